// round 1
// baseline (speedup 1.0000x reference)
#include <cuda_runtime.h>
#include <math.h>

// Problem constants (B=64, T=512, D=1024 from reference setup_inputs)
#define NB 64
#define NT 512
#define ND 1024
#define TV 506          // T - NM - 1
#define NMARG 5         // NM
#define TEMP_INV 10.0f  // 1/TEMP

#define TM 64
#define TN 64
#define KB 16

__device__ float  g_rnorm[NB * NT];
__device__ float  g_pos[NB * NT];
__device__ double g_acc;

// ---------------------------------------------------------------------------
__global__ void k_zero() { g_acc = 0.0; }

// One block per (b,t) row: rnorm = 1/max(||h||,1e-12)
__global__ void k_norm(const float* __restrict__ h) {
    int bt = blockIdx.x;
    const float4* p = (const float4*)(h + (size_t)bt * ND);
    float ss = 0.f;
#pragma unroll
    for (int i = 0; i < 2; i++) {
        float4 v = p[threadIdx.x + i * 128];
        ss += v.x * v.x + v.y * v.y + v.z * v.z + v.w * v.w;
    }
#pragma unroll
    for (int o = 16; o; o >>= 1) ss += __shfl_xor_sync(0xffffffffu, ss, o);
    __shared__ float sm[4];
    if ((threadIdx.x & 31) == 0) sm[threadIdx.x >> 5] = ss;
    __syncthreads();
    if (threadIdx.x == 0) {
        float tot = sm[0] + sm[1] + sm[2] + sm[3];
        g_rnorm[bt] = 1.0f / fmaxf(sqrtf(tot), 1e-12f);
    }
}

// One block per (b,t), t < TV: pos_score = (sum_off dot(f_t, f_{t+off}))/cnt/TEMP
__global__ void k_pos(const float* __restrict__ h) {
    int t = blockIdx.x;
    int b = blockIdx.y;
    const float4* a = (const float4*)(h + ((size_t)b * NT + t) * ND);
    float acc[4] = {0.f, 0.f, 0.f, 0.f};
    const int offs[4] = {-2, -1, 1, 2};
#pragma unroll
    for (int i = 0; i < 2; i++) {
        int idx = threadIdx.x + i * 128;
        float4 av = a[idx];
#pragma unroll
        for (int j = 0; j < 4; j++) {
            int tp = t + offs[j];
            if (tp >= 0 && tp < NT) {
                float4 pv = ((const float4*)(h + ((size_t)b * NT + tp) * ND))[idx];
                acc[j] += av.x * pv.x + av.y * pv.y + av.z * pv.z + av.w * pv.w;
            }
        }
    }
    float part = 0.f;
    int cnt = 0;
#pragma unroll
    for (int j = 0; j < 4; j++) {
        int tp = t + offs[j];
        if (tp >= 0 && tp < NT) { part += acc[j] * g_rnorm[b * NT + tp]; cnt++; }
    }
#pragma unroll
    for (int o = 16; o; o >>= 1) part += __shfl_xor_sync(0xffffffffu, part, o);
    __shared__ float sm[4];
    if ((threadIdx.x & 31) == 0) sm[threadIdx.x >> 5] = part;
    __syncthreads();
    if (threadIdx.x == 0) {
        float tot = sm[0] + sm[1] + sm[2] + sm[3];
        g_pos[b * NT + t] = tot * g_rnorm[b * NT + t] / (float)cnt * TEMP_INV;
    }
}

// Main: per block (b, t-tile of 64), loop non-masked s-tiles of 64,
// 64x64 scores via shared-tiled fp32 GEMM, streaming logsumexp over s.
__global__ __launch_bounds__(256) void k_main(const float* __restrict__ h) {
    __shared__ __align__(16) float As[KB][68];
    __shared__ __align__(16) float Bs[KB][68];

    int b = blockIdx.y;
    int t0 = blockIdx.x * TM;
    int tid = threadIdx.x;
    int ty = tid >> 4, tx = tid & 15;
    int tArow = ty * 4, tBcol = tx * 4;
    int lrow = tid >> 2;          // 0..63
    int lk = (tid & 3) * 4;       // 0,4,8,12

    const float* hb = h + (size_t)b * NT * ND;
    float rA = g_rnorm[b * NT + t0 + lrow];

    float m[4], z[4];
#pragma unroll
    for (int i = 0; i < 4; i++) { m[i] = -1e30f; z[i] = 0.f; }

    // first s-tile that contains any unmasked (t,s): s0+63 >= t0+NM
    int s0start = ((t0 + NMARG) / TN) * TN;

    for (int s0 = s0start; s0 < NT; s0 += TN) {
        float rB = g_rnorm[b * NT + s0 + lrow];
        float acc[4][4];
#pragma unroll
        for (int i = 0; i < 4; i++)
#pragma unroll
            for (int j = 0; j < 4; j++) acc[i][j] = 0.f;

        for (int k0 = 0; k0 < ND; k0 += KB) {
            __syncthreads();
            float4 av = *(const float4*)(hb + (size_t)(t0 + lrow) * ND + k0 + lk);
            As[lk + 0][lrow] = av.x * rA;
            As[lk + 1][lrow] = av.y * rA;
            As[lk + 2][lrow] = av.z * rA;
            As[lk + 3][lrow] = av.w * rA;
            float4 bv = *(const float4*)(hb + (size_t)(s0 + lrow) * ND + k0 + lk);
            Bs[lk + 0][lrow] = bv.x * rB;
            Bs[lk + 1][lrow] = bv.y * rB;
            Bs[lk + 2][lrow] = bv.z * rB;
            Bs[lk + 3][lrow] = bv.w * rB;
            __syncthreads();
#pragma unroll
            for (int k = 0; k < KB; k++) {
                float4 aa = *(const float4*)&As[k][tArow];
                float4 bb = *(const float4*)&Bs[k][tBcol];
                float aV[4] = {aa.x, aa.y, aa.z, aa.w};
                float bV[4] = {bb.x, bb.y, bb.z, bb.w};
#pragma unroll
                for (int i = 0; i < 4; i++)
#pragma unroll
                    for (int j = 0; j < 4; j++) acc[i][j] += aV[i] * bV[j];
            }
        }

        // fold this tile into the running per-row logsumexp
#pragma unroll
        for (int i = 0; i < 4; i++) {
            int t = t0 + tArow + i;
#pragma unroll
            for (int j = 0; j < 4; j++) {
                int s = s0 + tBcol + j;
                if (t < TV && s >= t + NMARG) {
                    float sc = acc[i][j] * TEMP_INV;
                    if (sc > m[i]) {
                        z[i] = z[i] * expf(m[i] - sc) + 1.f;
                        m[i] = sc;
                    } else {
                        z[i] += expf(sc - m[i]);
                    }
                }
            }
        }
    }

    // merge (m,z) across the 16 tx lanes owning the same t rows
#pragma unroll
    for (int off = 8; off >= 1; off >>= 1) {
#pragma unroll
        for (int i = 0; i < 4; i++) {
            float m2 = __shfl_xor_sync(0xffffffffu, m[i], off);
            float z2 = __shfl_xor_sync(0xffffffffu, z[i], off);
            float mm = fmaxf(m[i], m2);
            // finite -1e30 sentinel: exp(-1e30 - mm) underflows to 0, no NaN
            z[i] = z[i] * expf(m[i] - mm) + z2 * expf(m2 - mm);
            m[i] = mm;
        }
    }

    __shared__ float red[16];
    if (tx == 0) {
        float local = 0.f;
#pragma unroll
        for (int i = 0; i < 4; i++) {
            int t = t0 + tArow + i;
            if (t < TV) {
                float ps = g_pos[b * NT + t];
                float mm = fmaxf(m[i], ps);
                float zz = z[i] * expf(m[i] - mm) + expf(ps - mm);
                local += (mm + logf(zz)) - ps;
            }
        }
        red[ty] = local;
    }
    __syncthreads();
    if (tid == 0) {
        float tot = 0.f;
#pragma unroll
        for (int i = 0; i < 16; i++) tot += red[i];
        atomicAdd(&g_acc, (double)tot);
    }
}

__global__ void k_final(float* out) {
    out[0] = (float)(g_acc / (double)((size_t)NB * TV));
}

// ---------------------------------------------------------------------------
extern "C" void kernel_launch(void* const* d_in, const int* in_sizes, int n_in,
                              void* d_out, int out_size) {
    const float* h = (const float*)d_in[0];
    (void)in_sizes; (void)n_in; (void)out_size;

    k_zero<<<1, 1>>>();
    k_norm<<<NB * NT, 128>>>(h);
    k_pos<<<dim3(TV, NB), 128>>>(h);
    k_main<<<dim3(NT / TM, NB), 256>>>(h);
    k_final<<<1, 1>>>((float*)d_out);
}

// round 4
// speedup vs baseline: 5.1810x; 5.1810x over previous
#include <cuda_runtime.h>
#include <cuda_bf16.h>
#include <math.h>
#include <stdint.h>

#define NB 64
#define NT 512
#define ND 1024
#define TV 506
#define NMARG 5
#define TEMP_INV 10.0f
#define NPAIR 10

// scratch (allocation-free rule: __device__ globals)
__device__ __nv_bfloat16 g_feat[(size_t)NB * NT * ND];   // 64 MB normalized bf16
__device__ float  g_rnorm[NB * NT];
__device__ float  g_pos[NB * NT];
__device__ float  g_pm[NB * NPAIR * 128];
__device__ float  g_pz[NB * NPAIR * 128];
__device__ double g_acc;

// pair p -> (t-tile k, s-tile j), 128x128 tiles, j >= k (diagonal-masked upper wedge)
__constant__ int c_tk[NPAIR] = {0,0,0,0, 1,1,1, 2,2, 3};
__constant__ int c_sj[NPAIR] = {0,1,2,3, 1,2,3, 2,3, 3};

__device__ __forceinline__ uint32_t smem_u32(const void* p) {
    uint32_t a;
    asm("{ .reg .u64 t; cvta.to.shared.u64 t, %1; cvt.u32.u64 %0, t; }"
        : "=r"(a) : "l"(p));
    return a;
}
__device__ __forceinline__ uint32_t swz(uint32_t off) {
    return off ^ ((off >> 3) & 0x70);
}

// ---------------------------------------------------------------- kernels
__global__ void k_zero() { g_acc = 0.0; }

// normalize row + write bf16 feats + store rnorm. one block per (b,t) row.
__global__ void k_norm(const float* __restrict__ h) {
    int bt = blockIdx.x;
    int tid = threadIdx.x;
    const float4* p = (const float4*)(h + (size_t)bt * ND);
    float4 v0 = p[tid];
    float4 v1 = p[tid + 128];
    float ss = v0.x*v0.x + v0.y*v0.y + v0.z*v0.z + v0.w*v0.w
             + v1.x*v1.x + v1.y*v1.y + v1.z*v1.z + v1.w*v1.w;
#pragma unroll
    for (int o = 16; o; o >>= 1) ss += __shfl_xor_sync(0xffffffffu, ss, o);
    __shared__ float sm[4];
    __shared__ float s_rn;
    if ((tid & 31) == 0) sm[tid >> 5] = ss;
    __syncthreads();
    if (tid == 0) {
        float tot = sm[0] + sm[1] + sm[2] + sm[3];
        float r = 1.0f / fmaxf(sqrtf(tot), 1e-12f);
        s_rn = r;
        g_rnorm[bt] = r;
    }
    __syncthreads();
    float r = s_rn;
    __nv_bfloat162* out = (__nv_bfloat162*)(g_feat + (size_t)bt * ND);
    out[2 * tid + 0]       = __floats2bfloat162_rn(v0.x * r, v0.y * r);
    out[2 * tid + 1]       = __floats2bfloat162_rn(v0.z * r, v0.w * r);
    out[256 + 2 * tid + 0] = __floats2bfloat162_rn(v1.x * r, v1.y * r);
    out[256 + 2 * tid + 1] = __floats2bfloat162_rn(v1.z * r, v1.w * r);
}

// pos_score (fp32, exact; verified rel_err 0 in R1)
__global__ void k_pos(const float* __restrict__ h) {
    int t = blockIdx.x;
    int b = blockIdx.y;
    const float4* a = (const float4*)(h + ((size_t)b * NT + t) * ND);
    float acc[4] = {0.f, 0.f, 0.f, 0.f};
    const int offs[4] = {-2, -1, 1, 2};
#pragma unroll
    for (int i = 0; i < 2; i++) {
        int idx = threadIdx.x + i * 128;
        float4 av = a[idx];
#pragma unroll
        for (int j = 0; j < 4; j++) {
            int tp = t + offs[j];
            if (tp >= 0 && tp < NT) {
                float4 pv = ((const float4*)(h + ((size_t)b * NT + tp) * ND))[idx];
                acc[j] += av.x * pv.x + av.y * pv.y + av.z * pv.z + av.w * pv.w;
            }
        }
    }
    float part = 0.f;
    int cnt = 0;
#pragma unroll
    for (int j = 0; j < 4; j++) {
        int tp = t + offs[j];
        if (tp >= 0 && tp < NT) { part += acc[j] * g_rnorm[b * NT + tp]; cnt++; }
    }
#pragma unroll
    for (int o = 16; o; o >>= 1) part += __shfl_xor_sync(0xffffffffu, part, o);
    __shared__ float sm[4];
    if ((threadIdx.x & 31) == 0) sm[threadIdx.x >> 5] = part;
    __syncthreads();
    if (threadIdx.x == 0) {
        float tot = sm[0] + sm[1] + sm[2] + sm[3];
        g_pos[b * NT + t] = tot * g_rnorm[b * NT + t] / (float)cnt * TEMP_INV;
    }
}

// -------------------------------------------------------- HMMA main kernel
// One block per (pair, batch). 128x128 scores = A(128 t-rows) . B(128 s-rows)^T,
// bf16 mma.sync m16n8k16, fp32 accum, fused masked streaming logsumexp.
__global__ void __launch_bounds__(256, 2) k_mma() {
    __shared__ __align__(128) char sA[128 * 128];   // 128 rows x 64 bf16 (SW128)
    __shared__ __align__(128) char sB[128 * 128];
    __shared__ float red_m[2][128];
    __shared__ float red_z[2][128];

    int tid = threadIdx.x;
    int lane = tid & 31;
    int wid = tid >> 5;
    int warp_m = wid >> 1;       // 0..3
    int warp_n = wid & 1;        // 0..1
    int p = blockIdx.x, b = blockIdx.y;
    int t0 = c_tk[p] * 128, s0 = c_sj[p] * 128;

    const char* fb = (const char*)(g_feat + (size_t)b * NT * ND);
    const char* fA = fb + (size_t)t0 * (ND * 2);
    const char* fB = fb + (size_t)s0 * (ND * 2);

    float acc[2][8][4];
#pragma unroll
    for (int i = 0; i < 2; i++)
#pragma unroll
        for (int j = 0; j < 8; j++)
#pragma unroll
            for (int e = 0; e < 4; e++) acc[i][j][e] = 0.f;

    uint32_t sAu = smem_u32(sA), sBu = smem_u32(sB);

    for (int kc = 0; kc < 16; kc++) {
        __syncthreads();
#pragma unroll
        for (int i = 0; i < 4; i++) {
            int idx = tid + i * 256;
            int row = idx >> 3, c = idx & 7;
            *(uint4*)(sA + swz(row * 128 + c * 16)) =
                *(const uint4*)(fA + (size_t)row * (ND * 2) + kc * 128 + c * 16);
            *(uint4*)(sB + swz(row * 128 + c * 16)) =
                *(const uint4*)(fB + (size_t)row * (ND * 2) + kc * 128 + c * 16);
        }
        __syncthreads();
#pragma unroll
        for (int ks = 0; ks < 4; ks++) {
            uint32_t a[2][4];
#pragma unroll
            for (int mf = 0; mf < 2; mf++) {
                int row = warp_m * 32 + mf * 16 + (lane & 15);
                int col = ks * 32 + (lane >> 4) * 16;
                uint32_t addr = sAu + swz(row * 128 + col);
                asm volatile(
                    "ldmatrix.sync.aligned.m8n8.x4.shared.b16 {%0,%1,%2,%3}, [%4];"
                    : "=r"(a[mf][0]), "=r"(a[mf][1]), "=r"(a[mf][2]), "=r"(a[mf][3])
                    : "r"(addr));
            }
            uint32_t bfr[4][4];
#pragma unroll
            for (int g = 0; g < 4; g++) {
                int row = warp_n * 64 + g * 16 + (lane & 7) + ((lane >> 4) << 3);
                int col = ks * 32 + ((lane >> 3) & 1) * 16;
                uint32_t addr = sBu + swz(row * 128 + col);
                asm volatile(
                    "ldmatrix.sync.aligned.m8n8.x4.shared.b16 {%0,%1,%2,%3}, [%4];"
                    : "=r"(bfr[g][0]), "=r"(bfr[g][1]), "=r"(bfr[g][2]), "=r"(bfr[g][3])
                    : "r"(addr));
            }
#pragma unroll
            for (int mf = 0; mf < 2; mf++)
#pragma unroll
                for (int nf = 0; nf < 8; nf++) {
                    uint32_t b0 = bfr[nf >> 1][(nf & 1) * 2];
                    uint32_t b1 = bfr[nf >> 1][(nf & 1) * 2 + 1];
                    asm volatile(
                        "mma.sync.aligned.m16n8k16.row.col.f32.bf16.bf16.f32 "
                        "{%0,%1,%2,%3}, {%4,%5,%6,%7}, {%8,%9}, {%0,%1,%2,%3};"
                        : "+f"(acc[mf][nf][0]), "+f"(acc[mf][nf][1]),
                          "+f"(acc[mf][nf][2]), "+f"(acc[mf][nf][3])
                        : "r"(a[mf][0]), "r"(a[mf][1]), "r"(a[mf][2]), "r"(a[mf][3]),
                          "r"(b0), "r"(b1));
                }
        }
    }

    // fused masked streaming logsumexp over this tile's 128 cols per row
    int q = lane >> 2, c2 = lane & 3;
#pragma unroll
    for (int mf = 0; mf < 2; mf++)
#pragma unroll
        for (int hf = 0; hf < 2; hf++) {
            int row = warp_m * 32 + mf * 16 + hf * 8 + q;
            int tg = t0 + row;
            float m = -1e30f, z = 0.f;
#pragma unroll
            for (int nf = 0; nf < 8; nf++)
#pragma unroll
                for (int e = 0; e < 2; e++) {
                    int sg = s0 + warp_n * 64 + nf * 8 + c2 * 2 + e;
                    if (tg < TV && sg >= tg + NMARG) {
                        float v = acc[mf][nf][hf * 2 + e] * TEMP_INV;
                        if (v > m) { z = z * __expf(m - v) + 1.f; m = v; }
                        else        z += __expf(v - m);
                    }
                }
            // merge across the 4 lanes of the quad (same row, different cols)
#pragma unroll
            for (int off = 1; off <= 2; off <<= 1) {
                float m2 = __shfl_xor_sync(0xffffffffu, m, off);
                float z2 = __shfl_xor_sync(0xffffffffu, z, off);
                float mm = fmaxf(m, m2);
                z = z * __expf(m - mm) + z2 * __expf(m2 - mm);
                m = mm;
            }
            if (c2 == 0) { red_m[warp_n][row] = m; red_z[warp_n][row] = z; }
        }
    __syncthreads();
    if (tid < 128) {
        float m0 = red_m[0][tid], z0 = red_z[0][tid];
        float m1 = red_m[1][tid], z1 = red_z[1][tid];
        float mm = fmaxf(m0, m1);
        float zz = z0 * __expf(m0 - mm) + z1 * __expf(m1 - mm);
        g_pm[(b * NPAIR + p) * 128 + tid] = mm;
        g_pz[(b * NPAIR + p) * 128 + tid] = zz;
    }
}

// merge tile partials per (b,t), fold pos, accumulate loss
__global__ void k_reduce() {
    int b = blockIdx.x;
    int t = threadIdx.x;     // 512 threads
    float loss = 0.f;
    if (t < TV) {
        int k = t >> 7;
        const int ps_[5] = {0, 4, 7, 9, 10};
        float m = -1e30f, z = 0.f;
        for (int p = ps_[k]; p < ps_[k + 1]; p++) {
            float mp = g_pm[(b * NPAIR + p) * 128 + (t & 127)];
            float zp = g_pz[(b * NPAIR + p) * 128 + (t & 127)];
            float mm = fmaxf(m, mp);
            z = z * expf(m - mm) + zp * expf(mp - mm);
            m = mm;
        }
        float pscore = g_pos[b * NT + t];
        float mm = fmaxf(m, pscore);
        float zz = z * expf(m - mm) + expf(pscore - mm);
        loss = mm + logf(zz) - pscore;
    }
#pragma unroll
    for (int o = 16; o; o >>= 1) loss += __shfl_xor_sync(0xffffffffu, loss, o);
    __shared__ float sm[16];
    if ((t & 31) == 0) sm[t >> 5] = loss;
    __syncthreads();
    if (t == 0) {
        float tot = 0.f;
#pragma unroll
        for (int i = 0; i < 16; i++) tot += sm[i];
        atomicAdd(&g_acc, (double)tot);
    }
}

__global__ void k_final(float* out) {
    out[0] = (float)(g_acc / (double)((size_t)NB * TV));
}

// ---------------------------------------------------------------- launch
extern "C" void kernel_launch(void* const* d_in, const int* in_sizes, int n_in,
                              void* d_out, int out_size) {
    const float* h = (const float*)d_in[0];
    (void)in_sizes; (void)n_in; (void)out_size;

    k_zero<<<1, 1>>>();
    k_norm<<<NB * NT, 128>>>(h);
    k_pos<<<dim3(TV, NB), 128>>>(h);
    k_mma<<<dim3(NPAIR, NB), 256>>>();
    k_reduce<<<NB, 512>>>();
    k_final<<<1, 1>>>((float*)d_out);
}

// round 5
// speedup vs baseline: 6.9263x; 1.3369x over previous
#include <cuda_runtime.h>
#include <cuda_bf16.h>
#include <math.h>
#include <stdint.h>

#define NB 64
#define NT 512
#define ND 1024
#define TV 506
#define NMARG 5
#define TEMP_INV 10.0f
#define NPAIR 10

// scratch (allocation-free rule: __device__ globals)
__device__ __nv_bfloat16 g_feat[(size_t)NB * NT * ND];   // 64 MB normalized bf16
__device__ float  g_d1[NB * NT];
__device__ float  g_d2[NB * NT];
__device__ float  g_pm[NB * NPAIR * 128];
__device__ float  g_pz[NB * NPAIR * 128];
__device__ double g_acc;

// pair p -> (t-tile k, s-tile j), 128x128 tiles, j >= k (upper wedge)
__constant__ int c_tk[NPAIR] = {0,0,0,0, 1,1,1, 2,2, 3};
__constant__ int c_sj[NPAIR] = {0,1,2,3, 1,2,3, 2,3, 3};

__device__ __forceinline__ uint32_t smem_u32(const void* p) {
    uint32_t a;
    asm("{ .reg .u64 t; cvta.to.shared.u64 t, %1; cvt.u32.u64 %0, t; }"
        : "=r"(a) : "l"(p));
    return a;
}
// SW64 swizzle for 64-byte rows: bits[5:4] ^= bits[9:8]>>? (std helper form)
__device__ __forceinline__ uint32_t swz64(uint32_t off) {
    return off ^ ((off >> 3) & 0x30);
}
__device__ __forceinline__ void cp16(uint32_t sdst, const void* gsrc) {
    asm volatile("cp.async.cg.shared.global [%0], [%1], 16;"
                 :: "r"(sdst), "l"(gsrc));
}
#define CP_COMMIT() asm volatile("cp.async.commit_group;" ::: "memory")
#define CP_WAIT1()  asm volatile("cp.async.wait_group 1;" ::: "memory")
#define CP_WAIT0()  asm volatile("cp.async.wait_group 0;" ::: "memory")

// ---------------------------------------------------------------- kernels
// normalize row + write bf16 feats; block 0 also zeroes the accumulator.
__global__ void k_norm(const float* __restrict__ h) {
    int bt = blockIdx.x;
    int tid = threadIdx.x;
    if (bt == 0 && tid == 0) g_acc = 0.0;
    const float4* p = (const float4*)(h + (size_t)bt * ND);
    float4 v0 = p[tid];
    float4 v1 = p[tid + 128];
    float ss = v0.x*v0.x + v0.y*v0.y + v0.z*v0.z + v0.w*v0.w
             + v1.x*v1.x + v1.y*v1.y + v1.z*v1.z + v1.w*v1.w;
#pragma unroll
    for (int o = 16; o; o >>= 1) ss += __shfl_xor_sync(0xffffffffu, ss, o);
    __shared__ float sm[4];
    __shared__ float s_rn;
    if ((tid & 31) == 0) sm[tid >> 5] = ss;
    __syncthreads();
    if (tid == 0) {
        float tot = sm[0] + sm[1] + sm[2] + sm[3];
        s_rn = 1.0f / fmaxf(sqrtf(tot), 1e-12f);
    }
    __syncthreads();
    float r = s_rn;
    __nv_bfloat162* out = (__nv_bfloat162*)(g_feat + (size_t)bt * ND);
    out[2 * tid + 0]       = __floats2bfloat162_rn(v0.x * r, v0.y * r);
    out[2 * tid + 1]       = __floats2bfloat162_rn(v0.z * r, v0.w * r);
    out[256 + 2 * tid + 0] = __floats2bfloat162_rn(v1.x * r, v1.y * r);
    out[256 + 2 * tid + 1] = __floats2bfloat162_rn(v1.z * r, v1.w * r);
}

// d1[t]=f_t.f_{t+1}, d2[t]=f_t.f_{t+2} from bf16 feats. block per (t,b), t<TV.
__global__ void k_pos2() {
    int t = blockIdx.x;
    int b = blockIdx.y;
    int tid = threadIdx.x;       // 128 threads, 1 uint4 (8 bf16) each
    const __nv_bfloat16* base = g_feat + ((size_t)b * NT + t) * ND;
    uint4 a  = ((const uint4*)base)[tid];
    uint4 p1 = ((const uint4*)(base + ND))[tid];
    uint4 p2 = ((const uint4*)(base + 2 * ND))[tid];
    float d1 = 0.f, d2 = 0.f;
    const uint32_t* au = (const uint32_t*)&a;
    const uint32_t* q1 = (const uint32_t*)&p1;
    const uint32_t* q2 = (const uint32_t*)&p2;
#pragma unroll
    for (int i = 0; i < 4; i++) {
        float2 af = __bfloat1622float2(*(const __nv_bfloat162*)&au[i]);
        float2 f1 = __bfloat1622float2(*(const __nv_bfloat162*)&q1[i]);
        float2 f2 = __bfloat1622float2(*(const __nv_bfloat162*)&q2[i]);
        d1 += af.x * f1.x + af.y * f1.y;
        d2 += af.x * f2.x + af.y * f2.y;
    }
#pragma unroll
    for (int o = 16; o; o >>= 1) {
        d1 += __shfl_xor_sync(0xffffffffu, d1, o);
        d2 += __shfl_xor_sync(0xffffffffu, d2, o);
    }
    __shared__ float s1[4], s2[4];
    if ((tid & 31) == 0) { s1[tid >> 5] = d1; s2[tid >> 5] = d2; }
    __syncthreads();
    if (tid == 0) {
        g_d1[b * NT + t] = s1[0] + s1[1] + s1[2] + s1[3];
        g_d2[b * NT + t] = s2[0] + s2[1] + s2[2] + s2[3];
    }
}

// -------------------------------------------------------- pipelined HMMA
// 128x128 tile per block; K staged in 32 chunks of 32 elems (64B rows, SW64),
// cp.async double buffered. 8 warps: warp tile 32(t) x 64(s).
#define STG 8192   // bytes per stage per operand (128 rows x 64B)

__device__ __forceinline__ void stage_issue(
    uint32_t sAu, uint32_t sBu, int buf,
    const char* fA, const char* fB, int st, int tid) {
    int kb = st * 64;
#pragma unroll
    for (int i = 0; i < 2; i++) {
        int l = tid + i * 256;
        int row = l >> 2, u = l & 3;
        cp16(sAu + buf * STG + swz64(row * 64 + u * 16),
             fA + (size_t)row * 2048 + kb + u * 16);
    }
#pragma unroll
    for (int i = 0; i < 2; i++) {
        int l = tid + i * 256;
        int row = l >> 2, u = l & 3;
        cp16(sBu + buf * STG + swz64(row * 64 + u * 16),
             fB + (size_t)row * 2048 + kb + u * 16);
    }
}

__device__ __forceinline__ void stage_compute(
    uint32_t sAu, uint32_t sBu, int buf,
    int lane, int warp_m, int warp_n, float (*acc)[8][4]) {
#pragma unroll
    for (int ks = 0; ks < 2; ks++) {
        uint32_t a[2][4];
#pragma unroll
        for (int mf = 0; mf < 2; mf++) {
            int row = warp_m * 32 + mf * 16 + (lane & 15);
            int col = ks * 32 + (lane >> 4) * 16;
            uint32_t addr = sAu + buf * STG + swz64(row * 64 + col);
            asm volatile(
                "ldmatrix.sync.aligned.m8n8.x4.shared.b16 {%0,%1,%2,%3}, [%4];"
                : "=r"(a[mf][0]), "=r"(a[mf][1]), "=r"(a[mf][2]), "=r"(a[mf][3])
                : "r"(addr));
        }
        uint32_t bfr[4][4];
#pragma unroll
        for (int g = 0; g < 4; g++) {
            int row = warp_n * 64 + g * 16 + (lane & 7) + ((lane >> 4) << 3);
            int col = ks * 32 + ((lane >> 3) & 1) * 16;
            uint32_t addr = sBu + buf * STG + swz64(row * 64 + col);
            asm volatile(
                "ldmatrix.sync.aligned.m8n8.x4.shared.b16 {%0,%1,%2,%3}, [%4];"
                : "=r"(bfr[g][0]), "=r"(bfr[g][1]), "=r"(bfr[g][2]), "=r"(bfr[g][3])
                : "r"(addr));
        }
#pragma unroll
        for (int mf = 0; mf < 2; mf++)
#pragma unroll
            for (int nf = 0; nf < 8; nf++) {
                uint32_t b0 = bfr[nf >> 1][(nf & 1) * 2];
                uint32_t b1 = bfr[nf >> 1][(nf & 1) * 2 + 1];
                asm volatile(
                    "mma.sync.aligned.m16n8k16.row.col.f32.bf16.bf16.f32 "
                    "{%0,%1,%2,%3}, {%4,%5,%6,%7}, {%8,%9}, {%0,%1,%2,%3};"
                    : "+f"(acc[mf][nf][0]), "+f"(acc[mf][nf][1]),
                      "+f"(acc[mf][nf][2]), "+f"(acc[mf][nf][3])
                    : "r"(a[mf][0]), "r"(a[mf][1]), "r"(a[mf][2]), "r"(a[mf][3]),
                      "r"(b0), "r"(b1));
            }
    }
}

__global__ void __launch_bounds__(256, 2) k_mma() {
    __shared__ __align__(128) char sA[2][STG];
    __shared__ __align__(128) char sB[2][STG];
    __shared__ float red_m[2][128];
    __shared__ float red_z[2][128];

    int tid = threadIdx.x;
    int lane = tid & 31;
    int wid = tid >> 5;
    int warp_m = wid >> 1;       // 0..3
    int warp_n = wid & 1;        // 0..1
    int p = blockIdx.x, b = blockIdx.y;
    int t0 = c_tk[p] * 128, s0 = c_sj[p] * 128;

    const char* fb = (const char*)(g_feat + (size_t)b * NT * ND);
    const char* fA = fb + (size_t)t0 * (ND * 2);
    const char* fB = fb + (size_t)s0 * (ND * 2);

    float acc[2][8][4];
#pragma unroll
    for (int i = 0; i < 2; i++)
#pragma unroll
        for (int j = 0; j < 8; j++)
#pragma unroll
            for (int e = 0; e < 4; e++) acc[i][j][e] = 0.f;

    uint32_t sAu = smem_u32(sA), sBu = smem_u32(sB);

    stage_issue(sAu, sBu, 0, fA, fB, 0, tid);
    CP_COMMIT();
#pragma unroll 2
    for (int st = 0; st < 32; st++) {
        int buf = st & 1;
        if (st < 31) {
            stage_issue(sAu, sBu, buf ^ 1, fA, fB, st + 1, tid);
            CP_COMMIT();
            CP_WAIT1();
        } else {
            CP_WAIT0();
        }
        __syncthreads();
        stage_compute(sAu, sBu, buf, lane, warp_m, warp_n, acc);
        __syncthreads();
    }

    // fused masked streaming logsumexp over this tile's 128 cols per row
    int q = lane >> 2, c2 = lane & 3;
#pragma unroll
    for (int mf = 0; mf < 2; mf++)
#pragma unroll
        for (int hf = 0; hf < 2; hf++) {
            int row = warp_m * 32 + mf * 16 + hf * 8 + q;
            int tg = t0 + row;
            float m = -1e30f, z = 0.f;
#pragma unroll
            for (int nf = 0; nf < 8; nf++)
#pragma unroll
                for (int e = 0; e < 2; e++) {
                    int sg = s0 + warp_n * 64 + nf * 8 + c2 * 2 + e;
                    if (tg < TV && sg >= tg + NMARG) {
                        float v = acc[mf][nf][hf * 2 + e] * TEMP_INV;
                        if (v > m) { z = z * __expf(m - v) + 1.f; m = v; }
                        else        z += __expf(v - m);
                    }
                }
#pragma unroll
            for (int off = 1; off <= 2; off <<= 1) {
                float m2 = __shfl_xor_sync(0xffffffffu, m, off);
                float z2 = __shfl_xor_sync(0xffffffffu, z, off);
                float mm = fmaxf(m, m2);
                z = z * __expf(m - mm) + z2 * __expf(m2 - mm);
                m = mm;
            }
            if (c2 == 0) { red_m[warp_n][row] = m; red_z[warp_n][row] = z; }
        }
    __syncthreads();
    if (tid < 128) {
        float m0 = red_m[0][tid], z0 = red_z[0][tid];
        float m1 = red_m[1][tid], z1 = red_z[1][tid];
        float mm = fmaxf(m0, m1);
        float zz = z0 * __expf(m0 - mm) + z1 * __expf(m1 - mm);
        g_pm[(b * NPAIR + p) * 128 + tid] = mm;
        g_pz[(b * NPAIR + p) * 128 + tid] = zz;
    }
}

// merge tile partials per (b,t), build pos from d1/d2, accumulate loss
__global__ void k_reduce() {
    int b = blockIdx.x;
    int t = threadIdx.x;     // 512 threads
    float loss = 0.f;
    if (t < TV) {
        int k = t >> 7;
        const int ps_[5] = {0, 4, 7, 9, 10};
        float m = -1e30f, z = 0.f;
        for (int p = ps_[k]; p < ps_[k + 1]; p++) {
            float mp = g_pm[(b * NPAIR + p) * 128 + (t & 127)];
            float zp = g_pz[(b * NPAIR + p) * 128 + (t & 127)];
            float mm = fmaxf(m, mp);
            z = z * expf(m - mm) + zp * expf(mp - mm);
            m = mm;
        }
        // pos from adjacent-dot arrays
        float s = g_d1[b * NT + t] + g_d2[b * NT + t];
        int cnt = 2;
        if (t >= 1) { s += g_d1[b * NT + t - 1]; cnt++; }
        if (t >= 2) { s += g_d2[b * NT + t - 2]; cnt++; }
        float pscore = s / (float)cnt * TEMP_INV;
        float mm = fmaxf(m, pscore);
        float zz = z * expf(m - mm) + expf(pscore - mm);
        loss = mm + logf(zz) - pscore;
    }
#pragma unroll
    for (int o = 16; o; o >>= 1) loss += __shfl_xor_sync(0xffffffffu, loss, o);
    __shared__ float sm[16];
    if ((t & 31) == 0) sm[t >> 5] = loss;
    __syncthreads();
    if (t == 0) {
        float tot = 0.f;
#pragma unroll
        for (int i = 0; i < 16; i++) tot += sm[i];
        atomicAdd(&g_acc, (double)tot);
    }
}

__global__ void k_final(float* out) {
    out[0] = (float)(g_acc / (double)((size_t)NB * TV));
}

// ---------------------------------------------------------------- launch
extern "C" void kernel_launch(void* const* d_in, const int* in_sizes, int n_in,
                              void* d_out, int out_size) {
    const float* h = (const float*)d_in[0];
    (void)in_sizes; (void)n_in; (void)out_size;

    k_norm<<<NB * NT, 128>>>(h);
    k_pos2<<<dim3(TV, NB), 128>>>();
    k_mma<<<dim3(NPAIR, NB), 256>>>();
    k_reduce<<<NB, 512>>>();
    k_final<<<1, 1>>>((float*)d_out);
}

// round 6
// speedup vs baseline: 6.9784x; 1.0075x over previous
#include <cuda_runtime.h>
#include <cuda_bf16.h>
#include <math.h>
#include <stdint.h>

#define NB 64
#define NT 512
#define ND 1024
#define TV 506
#define NMARG 5
#define TEMP_INV 10.0f
#define NPAIR 10

// scratch (allocation-free rule: __device__ globals)
__device__ __nv_bfloat16 g_feat[(size_t)NB * NT * ND];   // 64 MB normalized bf16
__device__ float    g_d1[NB * NT];
__device__ float    g_d2[NB * NT];
__device__ float    g_pm[NB * NPAIR * 128];
__device__ float    g_pz[NB * NPAIR * 128];
__device__ double   g_acc;
__device__ unsigned g_done = 0;

// pair p -> (t-tile k, s-tile j), 128x128 tiles, j >= k (upper wedge)
__constant__ int c_tk[NPAIR] = {0,0,0,0, 1,1,1, 2,2, 3};
__constant__ int c_sj[NPAIR] = {0,1,2,3, 1,2,3, 2,3, 3};

__device__ __forceinline__ uint32_t smem_u32(const void* p) {
    uint32_t a;
    asm("{ .reg .u64 t; cvta.to.shared.u64 t, %1; cvt.u32.u64 %0, t; }"
        : "=r"(a) : "l"(p));
    return a;
}
__device__ __forceinline__ uint32_t swz64(uint32_t off) {
    return off ^ ((off >> 3) & 0x30);
}
__device__ __forceinline__ void cp16(uint32_t sdst, const void* gsrc) {
    asm volatile("cp.async.cg.shared.global [%0], [%1], 16;"
                 :: "r"(sdst), "l"(gsrc));
}
#define CP_COMMIT() asm volatile("cp.async.commit_group;" ::: "memory")
#define CP_WAIT1()  asm volatile("cp.async.wait_group 1;" ::: "memory")
#define CP_WAIT0()  asm volatile("cp.async.wait_group 0;" ::: "memory")

// ---------------------------------------------------------------- kernels
// normalize row + write bf16 feats; block 0 also zeroes the accumulator.
__global__ void k_norm(const float* __restrict__ h) {
    int bt = blockIdx.x;
    int tid = threadIdx.x;
    if (bt == 0 && tid == 0) { g_acc = 0.0; g_done = 0; }
    const float4* p = (const float4*)(h + (size_t)bt * ND);
    float4 v0 = p[tid];
    float4 v1 = p[tid + 128];
    float ss = v0.x*v0.x + v0.y*v0.y + v0.z*v0.z + v0.w*v0.w
             + v1.x*v1.x + v1.y*v1.y + v1.z*v1.z + v1.w*v1.w;
#pragma unroll
    for (int o = 16; o; o >>= 1) ss += __shfl_xor_sync(0xffffffffu, ss, o);
    __shared__ float sm[4];
    __shared__ float s_rn;
    if ((tid & 31) == 0) sm[tid >> 5] = ss;
    __syncthreads();
    if (tid == 0) {
        float tot = sm[0] + sm[1] + sm[2] + sm[3];
        s_rn = 1.0f / fmaxf(sqrtf(tot), 1e-12f);
    }
    __syncthreads();
    float r = s_rn;
    __nv_bfloat162* out = (__nv_bfloat162*)(g_feat + (size_t)bt * ND);
    out[2 * tid + 0]       = __floats2bfloat162_rn(v0.x * r, v0.y * r);
    out[2 * tid + 1]       = __floats2bfloat162_rn(v0.z * r, v0.w * r);
    out[256 + 2 * tid + 0] = __floats2bfloat162_rn(v1.x * r, v1.y * r);
    out[256 + 2 * tid + 1] = __floats2bfloat162_rn(v1.z * r, v1.w * r);
}

// d1[t]=f_t.f_{t+1}, d2[t]=f_t.f_{t+2}. Block handles 4 consecutive t (smem reuse).
__global__ void k_pos2() {
    __shared__ __align__(16) char srows[6 * 2048];   // rows t0..t0+5
    int t0 = blockIdx.x * 4;
    int b = blockIdx.y;
    int tid = threadIdx.x;       // 128 threads
    int lane = tid & 31, w = tid >> 5;
    const char* base = (const char*)(g_feat + ((size_t)b * NT + t0) * ND);
    // load 6 rows x 2048B = 768 uint4; 6 per thread
#pragma unroll
    for (int i = 0; i < 6; i++) {
        int l = tid + i * 128;
        int row = l >> 7, c = l & 127;
        *(uint4*)(srows + row * 2048 + c * 16) =
            *(const uint4*)(base + (size_t)row * 2048 + c * 16);
    }
    __syncthreads();
    int t = t0 + w;              // warp w handles t0+w
    if (t < TV) {
        const uint4* r0 = (const uint4*)(srows + w * 2048);
        const uint4* r1 = (const uint4*)(srows + (w + 1) * 2048);
        const uint4* r2 = (const uint4*)(srows + (w + 2) * 2048);
        float d1 = 0.f, d2 = 0.f;
#pragma unroll
        for (int i = 0; i < 4; i++) {
            uint4 a = r0[lane + 32 * i];
            uint4 x = r1[lane + 32 * i];
            uint4 y = r2[lane + 32 * i];
            const uint32_t* au = (const uint32_t*)&a;
            const uint32_t* xu = (const uint32_t*)&x;
            const uint32_t* yu = (const uint32_t*)&y;
#pragma unroll
            for (int j = 0; j < 4; j++) {
                float2 af = __bfloat1622float2(*(const __nv_bfloat162*)&au[j]);
                float2 xf = __bfloat1622float2(*(const __nv_bfloat162*)&xu[j]);
                float2 yf = __bfloat1622float2(*(const __nv_bfloat162*)&yu[j]);
                d1 += af.x * xf.x + af.y * xf.y;
                d2 += af.x * yf.x + af.y * yf.y;
            }
        }
#pragma unroll
        for (int o = 16; o; o >>= 1) {
            d1 += __shfl_xor_sync(0xffffffffu, d1, o);
            d2 += __shfl_xor_sync(0xffffffffu, d2, o);
        }
        if (lane == 0) { g_d1[b * NT + t] = d1; g_d2[b * NT + t] = d2; }
    }
}

// -------------------------------------------------------- pipelined HMMA
// 128x128 tile per block; K in 32 chunks of 32 elems (64B rows, SW64),
// cp.async 3-stage ring, ONE __syncthreads per stage.
#define STGB 16384   // bytes per stage (A 8KB @ +0, B 8KB @ +8192)

__device__ __forceinline__ void stage_issue(
    uint32_t sPipe, int buf, const char* fA, const char* fB, int st, int tid) {
    int kb = st * 64;
    uint32_t sb = sPipe + buf * STGB;
#pragma unroll
    for (int i = 0; i < 2; i++) {
        int l = tid + i * 256;
        int row = l >> 2, u = l & 3;
        cp16(sb + swz64(row * 64 + u * 16),
             fA + (size_t)row * 2048 + kb + u * 16);
    }
#pragma unroll
    for (int i = 0; i < 2; i++) {
        int l = tid + i * 256;
        int row = l >> 2, u = l & 3;
        cp16(sb + 8192 + swz64(row * 64 + u * 16),
             fB + (size_t)row * 2048 + kb + u * 16);
    }
}

__device__ __forceinline__ void stage_compute(
    uint32_t sPipe, int buf, int lane, int warp_m, int warp_n,
    float (*acc)[8][4]) {
    uint32_t sAu = sPipe + buf * STGB;
    uint32_t sBu = sAu + 8192;
#pragma unroll
    for (int ks = 0; ks < 2; ks++) {
        uint32_t a[2][4];
#pragma unroll
        for (int mf = 0; mf < 2; mf++) {
            int row = warp_m * 32 + mf * 16 + (lane & 15);
            int col = ks * 32 + (lane >> 4) * 16;
            uint32_t addr = sAu + swz64(row * 64 + col);
            asm volatile(
                "ldmatrix.sync.aligned.m8n8.x4.shared.b16 {%0,%1,%2,%3}, [%4];"
                : "=r"(a[mf][0]), "=r"(a[mf][1]), "=r"(a[mf][2]), "=r"(a[mf][3])
                : "r"(addr));
        }
        uint32_t bfr[4][4];
#pragma unroll
        for (int g = 0; g < 4; g++) {
            int row = warp_n * 64 + g * 16 + (lane & 7) + ((lane >> 4) << 3);
            int col = ks * 32 + ((lane >> 3) & 1) * 16;
            uint32_t addr = sBu + swz64(row * 64 + col);
            asm volatile(
                "ldmatrix.sync.aligned.m8n8.x4.shared.b16 {%0,%1,%2,%3}, [%4];"
                : "=r"(bfr[g][0]), "=r"(bfr[g][1]), "=r"(bfr[g][2]), "=r"(bfr[g][3])
                : "r"(addr));
        }
#pragma unroll
        for (int mf = 0; mf < 2; mf++)
#pragma unroll
            for (int nf = 0; nf < 8; nf++) {
                uint32_t b0 = bfr[nf >> 1][(nf & 1) * 2];
                uint32_t b1 = bfr[nf >> 1][(nf & 1) * 2 + 1];
                asm volatile(
                    "mma.sync.aligned.m16n8k16.row.col.f32.bf16.bf16.f32 "
                    "{%0,%1,%2,%3}, {%4,%5,%6,%7}, {%8,%9}, {%0,%1,%2,%3};"
                    : "+f"(acc[mf][nf][0]), "+f"(acc[mf][nf][1]),
                      "+f"(acc[mf][nf][2]), "+f"(acc[mf][nf][3])
                    : "r"(a[mf][0]), "r"(a[mf][1]), "r"(a[mf][2]), "r"(a[mf][3]),
                      "r"(b0), "r"(b1));
            }
    }
}

__global__ void __launch_bounds__(256, 2) k_mma() {
    __shared__ __align__(128) char s_pipe[3][STGB];  // 49152B = static smem cap

    int tid = threadIdx.x;
    int lane = tid & 31;
    int wid = tid >> 5;
    int warp_m = wid >> 1;
    int warp_n = wid & 1;
    int p = blockIdx.x, b = blockIdx.y;
    int t0 = c_tk[p] * 128, s0 = c_sj[p] * 128;

    const char* fb = (const char*)(g_feat + (size_t)b * NT * ND);
    const char* fA = fb + (size_t)t0 * (ND * 2);
    const char* fB = fb + (size_t)s0 * (ND * 2);

    float acc[2][8][4];
#pragma unroll
    for (int i = 0; i < 2; i++)
#pragma unroll
        for (int j = 0; j < 8; j++)
#pragma unroll
            for (int e = 0; e < 4; e++) acc[i][j][e] = 0.f;

    uint32_t sPipe = smem_u32(s_pipe);

    stage_issue(sPipe, 0, fA, fB, 0, tid); CP_COMMIT();
    stage_issue(sPipe, 1, fA, fB, 1, tid); CP_COMMIT();

    int buf = 0, nxt = 2;
#pragma unroll 1
    for (int st = 0; st < 32; st++) {
        if (st < 30) {
            CP_WAIT1();               // stage st landed; st+1 in flight
            __syncthreads();          // readers of buf(nxt)=buf(st-1) are done
            stage_issue(sPipe, nxt, fA, fB, st + 2, tid);
            CP_COMMIT();
        } else {
            CP_WAIT0();
            __syncthreads();
        }
        stage_compute(sPipe, buf, lane, warp_m, warp_n, acc);
        buf = (buf == 2) ? 0 : buf + 1;
        nxt = (nxt == 2) ? 0 : nxt + 1;
    }

    // epilogue: masked streaming logsumexp; red arrays alias dead pipe smem
    __syncthreads();
    float* red_m = (float*)&s_pipe[0][0];      // [2][128]
    float* red_z = red_m + 256;                // [2][128]
    int q = lane >> 2, c2 = lane & 3;
#pragma unroll
    for (int mf = 0; mf < 2; mf++)
#pragma unroll
        for (int hf = 0; hf < 2; hf++) {
            int row = warp_m * 32 + mf * 16 + hf * 8 + q;
            int tg = t0 + row;
            float m = -1e30f, z = 0.f;
#pragma unroll
            for (int nf = 0; nf < 8; nf++)
#pragma unroll
                for (int e = 0; e < 2; e++) {
                    int sg = s0 + warp_n * 64 + nf * 8 + c2 * 2 + e;
                    if (tg < TV && sg >= tg + NMARG) {
                        float v = acc[mf][nf][hf * 2 + e] * TEMP_INV;
                        if (v > m) { z = z * __expf(m - v) + 1.f; m = v; }
                        else        z += __expf(v - m);
                    }
                }
#pragma unroll
            for (int off = 1; off <= 2; off <<= 1) {
                float m2 = __shfl_xor_sync(0xffffffffu, m, off);
                float z2 = __shfl_xor_sync(0xffffffffu, z, off);
                float mm = fmaxf(m, m2);
                z = z * __expf(m - mm) + z2 * __expf(m2 - mm);
                m = mm;
            }
            if (c2 == 0) {
                red_m[warp_n * 128 + row] = m;
                red_z[warp_n * 128 + row] = z;
            }
        }
    __syncthreads();
    if (tid < 128) {
        float m0 = red_m[tid],       z0 = red_z[tid];
        float m1 = red_m[128 + tid], z1 = red_z[128 + tid];
        float mm = fmaxf(m0, m1);
        float zz = z0 * __expf(m0 - mm) + z1 * __expf(m1 - mm);
        g_pm[(b * NPAIR + p) * 128 + tid] = mm;
        g_pz[(b * NPAIR + p) * 128 + tid] = zz;
    }
}

// merge tile partials per (b,t), build pos from d1/d2, accumulate loss;
// last block writes the final scalar (fused k_final).
__global__ void k_reduce(float* out) {
    int b = blockIdx.x;
    int t = threadIdx.x;     // 512 threads
    float loss = 0.f;
    if (t < TV) {
        int k = t >> 7;
        const int ps_[5] = {0, 4, 7, 9, 10};
        float m = -1e30f, z = 0.f;
        for (int p = ps_[k]; p < ps_[k + 1]; p++) {
            float mp = g_pm[(b * NPAIR + p) * 128 + (t & 127)];
            float zp = g_pz[(b * NPAIR + p) * 128 + (t & 127)];
            float mm = fmaxf(m, mp);
            z = z * expf(m - mm) + zp * expf(mp - mm);
            m = mm;
        }
        float s = g_d1[b * NT + t] + g_d2[b * NT + t];
        int cnt = 2;
        if (t >= 1) { s += g_d1[b * NT + t - 1]; cnt++; }
        if (t >= 2) { s += g_d2[b * NT + t - 2]; cnt++; }
        float pscore = s / (float)cnt * TEMP_INV;
        float mm = fmaxf(m, pscore);
        float zz = z * expf(m - mm) + expf(pscore - mm);
        loss = mm + logf(zz) - pscore;
    }
#pragma unroll
    for (int o = 16; o; o >>= 1) loss += __shfl_xor_sync(0xffffffffu, loss, o);
    __shared__ float sm[16];
    if ((t & 31) == 0) sm[t >> 5] = loss;
    __syncthreads();
    if (t == 0) {
        float tot = 0.f;
#pragma unroll
        for (int i = 0; i < 16; i++) tot += sm[i];
        atomicAdd(&g_acc, (double)tot);
        __threadfence();
        unsigned v = atomicAdd(&g_done, 1u);
        if (v == NB - 1) {
            out[0] = (float)(g_acc / (double)((size_t)NB * TV));
            g_done = 0;      // reset for next graph replay
        }
    }
}

// ---------------------------------------------------------------- launch
extern "C" void kernel_launch(void* const* d_in, const int* in_sizes, int n_in,
                              void* d_out, int out_size) {
    const float* h = (const float*)d_in[0];
    (void)in_sizes; (void)n_in; (void)out_size;

    k_norm<<<NB * NT, 128>>>(h);
    k_pos2<<<dim3((TV + 3) / 4, NB), 128>>>();
    k_mma<<<dim3(NPAIR, NB), 256>>>();
    k_reduce<<<NB, 512>>>((float*)d_out);
}

// round 8
// speedup vs baseline: 7.8751x; 1.1285x over previous
#include <cuda_runtime.h>
#include <cuda_bf16.h>
#include <math.h>
#include <stdint.h>

#define NB 64
#define NT 512
#define ND 1024
#define TV 506
#define NMARG 5
#define TEMP_INV 10.0f
#define NPAIR 10

// scratch (allocation-free rule: __device__ globals)
__device__ __nv_bfloat16 g_feat[(size_t)NB * NT * ND];   // 64 MB normalized bf16
__device__ float    g_d1[NB * NT];
__device__ float    g_d2[NB * NT];
__device__ float    g_pm[NB * NPAIR * 128];
__device__ float    g_pz[NB * NPAIR * 128];
__device__ double   g_acc;
__device__ unsigned g_done = 0;

// pair p -> (t-tile k, s-tile j), 128x128 tiles, j >= k (upper wedge)
__constant__ int c_tk[NPAIR] = {0,0,0,0, 1,1,1, 2,2, 3};
__constant__ int c_sj[NPAIR] = {0,1,2,3, 1,2,3, 2,3, 3};

__device__ __forceinline__ uint32_t smem_u32(const void* p) {
    uint32_t a;
    asm("{ .reg .u64 t; cvta.to.shared.u64 t, %1; cvt.u32.u64 %0, t; }"
        : "=r"(a) : "l"(p));
    return a;
}
__device__ __forceinline__ uint32_t swz64(uint32_t off) {
    return off ^ ((off >> 3) & 0x30);
}
__device__ __forceinline__ void cp16(uint32_t sdst, const void* gsrc) {
    asm volatile("cp.async.cg.shared.global [%0], [%1], 16;"
                 :: "r"(sdst), "l"(gsrc));
}
#define CP_COMMIT() asm volatile("cp.async.commit_group;" ::: "memory")
#define CP_WAIT1()  asm volatile("cp.async.wait_group 1;" ::: "memory")
#define CP_WAIT0()  asm volatile("cp.async.wait_group 0;" ::: "memory")

// ---------------------------------------------------------------- kernels
// normalize row + write bf16 feats; block 0 also zeroes the accumulator.
__global__ void k_norm(const float* __restrict__ h) {
    int bt = blockIdx.x;
    int tid = threadIdx.x;
    if (bt == 0 && tid == 0) { g_acc = 0.0; g_done = 0; }
    const float4* p = (const float4*)(h + (size_t)bt * ND);
    float4 v0 = p[tid];
    float4 v1 = p[tid + 128];
    float ss = v0.x*v0.x + v0.y*v0.y + v0.z*v0.z + v0.w*v0.w
             + v1.x*v1.x + v1.y*v1.y + v1.z*v1.z + v1.w*v1.w;
#pragma unroll
    for (int o = 16; o; o >>= 1) ss += __shfl_xor_sync(0xffffffffu, ss, o);
    __shared__ float sm[4];
    __shared__ float s_rn;
    if ((tid & 31) == 0) sm[tid >> 5] = ss;
    __syncthreads();
    if (tid == 0) {
        float tot = sm[0] + sm[1] + sm[2] + sm[3];
        s_rn = 1.0f / fmaxf(sqrtf(tot), 1e-12f);
    }
    __syncthreads();
    float r = s_rn;
    __nv_bfloat162* out = (__nv_bfloat162*)(g_feat + (size_t)bt * ND);
    out[2 * tid + 0]       = __floats2bfloat162_rn(v0.x * r, v0.y * r);
    out[2 * tid + 1]       = __floats2bfloat162_rn(v0.z * r, v0.w * r);
    out[256 + 2 * tid + 0] = __floats2bfloat162_rn(v1.x * r, v1.y * r);
    out[256 + 2 * tid + 1] = __floats2bfloat162_rn(v1.z * r, v1.w * r);
}

// -------------------------------------------------------- pipelined HMMA
// 128x128 tile per block; K in 32 chunks of 32 elems (64B rows, SW64),
// cp.async 3-stage ring, ONE __syncthreads per stage.
// Epilogue also harvests d1/d2 (pos-score dots) straight from the accumulators.
#define STGB 16384   // bytes per stage (A 8KB @ +0, B 8KB @ +8192)

__device__ __forceinline__ void stage_issue(
    uint32_t sPipe, int buf, const char* fA, const char* fB, int st, int tid) {
    int kb = st * 64;
    uint32_t sb = sPipe + buf * STGB;
#pragma unroll
    for (int i = 0; i < 2; i++) {
        int l = tid + i * 256;
        int row = l >> 2, u = l & 3;
        cp16(sb + swz64(row * 64 + u * 16),
             fA + (size_t)row * 2048 + kb + u * 16);
    }
#pragma unroll
    for (int i = 0; i < 2; i++) {
        int l = tid + i * 256;
        int row = l >> 2, u = l & 3;
        cp16(sb + 8192 + swz64(row * 64 + u * 16),
             fB + (size_t)row * 2048 + kb + u * 16);
    }
}

__device__ __forceinline__ void stage_compute(
    uint32_t sPipe, int buf, int lane, int warp_m, int warp_n,
    float (*acc)[8][4]) {
    uint32_t sAu = sPipe + buf * STGB;
    uint32_t sBu = sAu + 8192;
#pragma unroll
    for (int ks = 0; ks < 2; ks++) {
        uint32_t a[2][4];
#pragma unroll
        for (int mf = 0; mf < 2; mf++) {
            int row = warp_m * 32 + mf * 16 + (lane & 15);
            int col = ks * 32 + (lane >> 4) * 16;
            uint32_t addr = sAu + swz64(row * 64 + col);
            asm volatile(
                "ldmatrix.sync.aligned.m8n8.x4.shared.b16 {%0,%1,%2,%3}, [%4];"
                : "=r"(a[mf][0]), "=r"(a[mf][1]), "=r"(a[mf][2]), "=r"(a[mf][3])
                : "r"(addr));
        }
        uint32_t bfr[4][4];
#pragma unroll
        for (int g = 0; g < 4; g++) {
            int row = warp_n * 64 + g * 16 + (lane & 7) + ((lane >> 4) << 3);
            int col = ks * 32 + ((lane >> 3) & 1) * 16;
            uint32_t addr = sBu + swz64(row * 64 + col);
            asm volatile(
                "ldmatrix.sync.aligned.m8n8.x4.shared.b16 {%0,%1,%2,%3}, [%4];"
                : "=r"(bfr[g][0]), "=r"(bfr[g][1]), "=r"(bfr[g][2]), "=r"(bfr[g][3])
                : "r"(addr));
        }
#pragma unroll
        for (int mf = 0; mf < 2; mf++)
#pragma unroll
            for (int nf = 0; nf < 8; nf++) {
                uint32_t b0 = bfr[nf >> 1][(nf & 1) * 2];
                uint32_t b1 = bfr[nf >> 1][(nf & 1) * 2 + 1];
                asm volatile(
                    "mma.sync.aligned.m16n8k16.row.col.f32.bf16.bf16.f32 "
                    "{%0,%1,%2,%3}, {%4,%5,%6,%7}, {%8,%9}, {%0,%1,%2,%3};"
                    : "+f"(acc[mf][nf][0]), "+f"(acc[mf][nf][1]),
                      "+f"(acc[mf][nf][2]), "+f"(acc[mf][nf][3])
                    : "r"(a[mf][0]), "r"(a[mf][1]), "r"(a[mf][2]), "r"(a[mf][3]),
                      "r"(b0), "r"(b1));
            }
    }
}

__global__ void __launch_bounds__(256, 2) k_mma() {
    __shared__ __align__(128) char s_pipe[3][STGB];  // 49152B = static smem cap

    int tid = threadIdx.x;
    int lane = tid & 31;
    int wid = tid >> 5;
    int warp_m = wid >> 1;
    int warp_n = wid & 1;
    int p = blockIdx.x, b = blockIdx.y;
    int t0 = c_tk[p] * 128, s0 = c_sj[p] * 128;

    const char* fb = (const char*)(g_feat + (size_t)b * NT * ND);
    const char* fA = fb + (size_t)t0 * (ND * 2);
    const char* fB = fb + (size_t)s0 * (ND * 2);

    float acc[2][8][4];
#pragma unroll
    for (int i = 0; i < 2; i++)
#pragma unroll
        for (int j = 0; j < 8; j++)
#pragma unroll
            for (int e = 0; e < 4; e++) acc[i][j][e] = 0.f;

    uint32_t sPipe = smem_u32(s_pipe);

    stage_issue(sPipe, 0, fA, fB, 0, tid); CP_COMMIT();
    stage_issue(sPipe, 1, fA, fB, 1, tid); CP_COMMIT();

    int buf = 0, nxt = 2;
#pragma unroll 1
    for (int st = 0; st < 32; st++) {
        if (st < 30) {
            CP_WAIT1();
            __syncthreads();
            stage_issue(sPipe, nxt, fA, fB, st + 2, tid);
            CP_COMMIT();
        } else {
            CP_WAIT0();
            __syncthreads();
        }
        stage_compute(sPipe, buf, lane, warp_m, warp_n, acc);
        buf = (buf == 2) ? 0 : buf + 1;
        nxt = (nxt == 2) ? 0 : nxt + 1;
    }

    // epilogue: masked streaming logsumexp + harvest d1/d2 from accumulators
    __syncthreads();
    float* red_m = (float*)&s_pipe[0][0];      // [2][128]
    float* red_z = red_m + 256;                // [2][128]
    int q = lane >> 2, c2 = lane & 3;
#pragma unroll
    for (int mf = 0; mf < 2; mf++)
#pragma unroll
        for (int hf = 0; hf < 2; hf++) {
            int row = warp_m * 32 + mf * 16 + hf * 8 + q;
            int tg = t0 + row;
            float m = -1e30f, z = 0.f;
#pragma unroll
            for (int nf = 0; nf < 8; nf++)
#pragma unroll
                for (int e = 0; e < 2; e++) {
                    int sg = s0 + warp_n * 64 + nf * 8 + c2 * 2 + e;
                    float raw = acc[mf][nf][hf * 2 + e];
                    int d = sg - tg;
                    // d1/d2 harvest: each (t,t+1)/(t,t+2) lives in exactly one block
                    if (d == 1) g_d1[b * NT + tg] = raw;
                    if (d == 2) g_d2[b * NT + tg] = raw;
                    if (tg < TV && d >= NMARG) {
                        float v = raw * TEMP_INV;
                        if (v > m) { z = z * __expf(m - v) + 1.f; m = v; }
                        else        z += __expf(v - m);
                    }
                }
#pragma unroll
            for (int off = 1; off <= 2; off <<= 1) {
                float m2 = __shfl_xor_sync(0xffffffffu, m, off);
                float z2 = __shfl_xor_sync(0xffffffffu, z, off);
                float mm = fmaxf(m, m2);
                z = z * __expf(m - mm) + z2 * __expf(m2 - mm);
                m = mm;
            }
            if (c2 == 0) {
                red_m[warp_n * 128 + row] = m;
                red_z[warp_n * 128 + row] = z;
            }
        }
    __syncthreads();
    if (tid < 128) {
        float m0 = red_m[tid],       z0 = red_z[tid];
        float m1 = red_m[128 + tid], z1 = red_z[128 + tid];
        float mm = fmaxf(m0, m1);
        float zz = z0 * __expf(m0 - mm) + z1 * __expf(m1 - mm);
        g_pm[(b * NPAIR + p) * 128 + tid] = mm;
        g_pz[(b * NPAIR + p) * 128 + tid] = zz;
    }
}

// merge tile partials per (b,t-group), build pos from d1/d2, accumulate loss;
// last block writes the final scalar.
__global__ void k_reduce(float* out) {
    int b = blockIdx.x;
    int k = blockIdx.y;          // t-group 0..3
    int t = k * 128 + threadIdx.x;   // 128 threads
    float loss = 0.f;
    if (t < TV) {
        const int ps_[5] = {0, 4, 7, 9, 10};
        float m = -1e30f, z = 0.f;
        for (int p = ps_[k]; p < ps_[k + 1]; p++) {
            float mp = g_pm[(b * NPAIR + p) * 128 + threadIdx.x];
            float zp = g_pz[(b * NPAIR + p) * 128 + threadIdx.x];
            float mm = fmaxf(m, mp);
            z = z * expf(m - mm) + zp * expf(mp - mm);
            m = mm;
        }
        float s = g_d1[b * NT + t] + g_d2[b * NT + t];
        int cnt = 2;
        if (t >= 1) { s += g_d1[b * NT + t - 1]; cnt++; }
        if (t >= 2) { s += g_d2[b * NT + t - 2]; cnt++; }
        float pscore = s / (float)cnt * TEMP_INV;
        float mm = fmaxf(m, pscore);
        float zz = z * expf(m - mm) + expf(pscore - mm);
        loss = mm + logf(zz) - pscore;
    }
#pragma unroll
    for (int o = 16; o; o >>= 1) loss += __shfl_xor_sync(0xffffffffu, loss, o);
    __shared__ float sm[4];
    if ((threadIdx.x & 31) == 0) sm[threadIdx.x >> 5] = loss;
    __syncthreads();
    if (threadIdx.x == 0) {
        float tot = sm[0] + sm[1] + sm[2] + sm[3];
        atomicAdd(&g_acc, (double)tot);
        __threadfence();
        unsigned v = atomicAdd(&g_done, 1u);
        if (v == NB * 4 - 1) {
            out[0] = (float)(g_acc / (double)((size_t)NB * TV));
            g_done = 0;      // reset for next graph replay
        }
    }
}

// ---------------------------------------------------------------- launch
extern "C" void kernel_launch(void* const* d_in, const int* in_sizes, int n_in,
                              void* d_out, int out_size) {
    const float* h = (const float*)d_in[0];
    (void)in_sizes; (void)n_in; (void)out_size;

    k_norm<<<NB * NT, 128>>>(h);
    k_mma<<<dim3(NPAIR, NB), 256>>>();
    k_reduce<<<dim3(NB, 4), 128>>>((float*)d_out);
}